// round 12
// baseline (speedup 1.0000x reference)
#include <cuda_runtime.h>
#include <cuda_bf16.h>

// Fixed problem shapes
#define N_C 500000
#define N_F 2000000
#define KNBR 8
#define ROWW (KNBR + 2)   // 8 neighbor cols + pad + count
#define TPB 256

// Scratch: d = input - pred, padded to float4 (16B-aligned single-sector gathers).
__device__ float4 g_d[N_C + N_F];
__device__ double g_acc;
__device__ unsigned int g_done;

// ---------------------------------------------------------------------------
// diff for one mesh: d = input - pred (float4 loads + smem transpose).
// reset!=0: block 0 thread 0 also resets accumulator/done-counter.
// ---------------------------------------------------------------------------
__global__ void diff_kernel(const float* __restrict__ a,
                            const float* __restrict__ p,
                            int n, int segbase, int reset) {
    const int t = threadIdx.x;
    const int b = blockIdx.x;
    if (reset && b == 0 && t == 0) { g_acc = 0.0; g_done = 0u; }

    const int v0 = b * TPB;
    __shared__ float s[3 * TPB];

    if (v0 + TPB <= n) {
        // Full block: 256 vertices = 768 floats = 192 float4 per array.
        const int f4base = (v0 >> 2) * 3;  // exact: v0 % 4 == 0
        if (t < 3 * TPB / 4) {
            float4 av = __ldcs((const float4*)a + f4base + t);
            float4 pv = __ldcs((const float4*)p + f4base + t);
            ((float4*)s)[t] = make_float4(av.x - pv.x, av.y - pv.y,
                                          av.z - pv.z, av.w - pv.w);
        }
        __syncthreads();
        // stride-3 smem reads: gcd(3,32)=1 -> conflict-free
        g_d[segbase + v0 + t] =
            make_float4(s[3 * t], s[3 * t + 1], s[3 * t + 2], 0.0f);
    } else {
        const int i = v0 + t;
        if (i < n) {
            const int b3 = 3 * i;
            g_d[segbase + i] = make_float4(a[b3 + 0] - p[b3 + 0],
                                           a[b3 + 1] - p[b3 + 1],
                                           a[b3 + 2] - p[b3 + 2], 0.0f);
        }
    }
}

// ---------------------------------------------------------------------------
// Loss kernel (one mesh per launch):
//   e = d[i] - (sum_valid d[idx[j]]) / count ;  v = ||e||^2
//   block-reduce -> atomicAdd(double, scaled).
// The block that takes g_done to total_blocks writes the result (the fine
// loss launch depends on the coarse one in every schedule below, so that
// block always lives in the fine launch).
// ---------------------------------------------------------------------------
__global__ void loss_kernel(const int* __restrict__ lap, int n, int base,
                            double scale, unsigned int total_blocks,
                            float* __restrict__ out) {
    const int i = blockIdx.x * TPB + threadIdx.x;
    float v = 0.0f;
    if (i < n) {
        const float4* __restrict__ d = g_d + base;
        const float4 di = d[i];

        // 40B row = 5 x int2 (8B aligned); __ldcs: one-shot stream,
        // keep L2 for the g_d gather region.
        const int2* __restrict__ r2 = (const int2*)lap + (size_t)i * 5;
        const int2 p0 = __ldcs(r2 + 0);
        const int2 p1 = __ldcs(r2 + 1);
        const int2 p2 = __ldcs(r2 + 2);
        const int2 p3 = __ldcs(r2 + 3);
        const int2 p4 = __ldcs(r2 + 4);  // p4.y = count
        int idx[KNBR] = {p0.x, p0.y, p1.x, p1.y, p2.x, p2.y, p3.x, p3.y};

        float sx = 0.0f, sy = 0.0f, sz = 0.0f;
#pragma unroll
        for (int j = 0; j < KNBR; j++) {
            const int id = idx[j];
            if (id >= 0) {
                const float4 nv = d[id];
                sx += nv.x; sy += nv.y; sz += nv.z;
            }
        }
        const float inv = 1.0f / (float)p4.y;
        const float ex = di.x - sx * inv;
        const float ey = di.y - sy * inv;
        const float ez = di.z - sz * inv;
        v = ex * ex + ey * ey + ez * ez;
    }

    // intra-block reduction
#pragma unroll
    for (int off = 16; off > 0; off >>= 1)
        v += __shfl_down_sync(0xFFFFFFFFu, v, off);

    __shared__ float warp_sums[TPB / 32];
    __shared__ bool is_last;
    const int lane = threadIdx.x & 31;
    const int wid  = threadIdx.x >> 5;
    if (lane == 0) warp_sums[wid] = v;
    __syncthreads();

    if (wid == 0) {
        float s = (lane < (TPB >> 5)) ? warp_sums[lane] : 0.0f;
#pragma unroll
        for (int off = 4; off > 0; off >>= 1)
            s += __shfl_down_sync(0xFFFFFFFFu, s, off);
        if (lane == 0) {
            atomicAdd(&g_acc, (double)s * scale);
            __threadfence();
            unsigned int old = atomicAdd(&g_done, 1u);
            is_last = (old == total_blocks - 1u);
        }
    }
    __syncthreads();

    if (is_last && threadIdx.x == 0) {
        __threadfence();
        out[0] = (float)g_acc;
    }
}

extern "C" void kernel_launch(void* const* d_in, const int* in_sizes, int n_in,
                              void* d_out, int out_size) {
    const float* ci = (const float*)d_in[0];  // coarse_input  (N_C,3)
    const float* cp = (const float*)d_in[1];  // coarse_pred   (N_C,3)
    const float* fi = (const float*)d_in[2];  // fine_input    (N_F,3)
    const float* fp = (const float*)d_in[3];  // fine_pred     (N_F,3)
    const int* lic  = (const int*)d_in[4];    // lap_idx_coarse (N_C,10)
    const int* lif  = (const int*)d_in[5];    // lap_idx_fine   (N_F,10)

    const int nc = in_sizes[0] / 3;
    const int nf = in_sizes[2] / 3;

    const int cb = (nc + TPB - 1) / TPB;
    const int fb = (nf + TPB - 1) / TPB;
    const unsigned int total = (unsigned int)(cb + fb);

    const cudaStream_t s0 = (cudaStream_t)0;   // harness launch stream

    // Lazily create the side stream + events for the parallel graph branch.
    // NEVER create while capture is active (first call is the plain
    // correctness run, so creation normally happens there).
    static cudaStream_t s2 = nullptr;
    static cudaEvent_t e1 = nullptr, e3 = nullptr;
    static bool init_tried = false;
    if (!init_tried) {
        cudaStreamCaptureStatus st = cudaStreamCaptureStatusNone;
        cudaStreamIsCapturing(s0, &st);
        if (st == cudaStreamCaptureStatusNone) {
            init_tried = true;
            if (cudaStreamCreateWithFlags(&s2, cudaStreamNonBlocking) != cudaSuccess ||
                cudaEventCreateWithFlags(&e1, cudaEventDisableTiming) != cudaSuccess ||
                cudaEventCreateWithFlags(&e3, cudaEventDisableTiming) != cudaSuccess) {
                s2 = nullptr;  // fall back to sequential forever
            }
        }
    }

    if (s2 != nullptr) {
        // s0: diff_coarse -> e1 -> diff_fine -------------------\
        // s2:             e1 -> loss_coarse -> e3 -------------- > loss_fine (s0)
        diff_kernel<<<cb, TPB, 0, s0>>>(ci, cp, nc, 0, 1);
        cudaEventRecord(e1, s0);
        diff_kernel<<<fb, TPB, 0, s0>>>(fi, fp, nf, nc, 0);

        cudaStreamWaitEvent(s2, e1, 0);
        loss_kernel<<<cb, TPB, 0, s2>>>(lic, nc, 0, 0.5 / (double)nc, total,
                                        (float*)d_out);
        cudaEventRecord(e3, s2);

        cudaStreamWaitEvent(s0, e3, 0);
        loss_kernel<<<fb, TPB, 0, s0>>>(lif, nf, nc, 0.5 / (double)nf, total,
                                        (float*)d_out);
    } else {
        // Sequential fallback (identical math, same stream).
        diff_kernel<<<cb, TPB, 0, s0>>>(ci, cp, nc, 0, 1);
        diff_kernel<<<fb, TPB, 0, s0>>>(fi, fp, nf, nc, 0);
        loss_kernel<<<cb, TPB, 0, s0>>>(lic, nc, 0, 0.5 / (double)nc, total,
                                        (float*)d_out);
        loss_kernel<<<fb, TPB, 0, s0>>>(lif, nf, nc, 0.5 / (double)nf, total,
                                        (float*)d_out);
    }
}